// round 15
// baseline (speedup 1.0000x reference)
#include <cuda_runtime.h>
#include <cuda_bf16.h>
#include <math.h>
#include <cstdint>

#define NN 100000
#define EE 500000
#define ADJ_STRIDE 40   // max degree bucket; P(Poisson(5) >= 40) ~ 1e-23

typedef unsigned int u32;

// ---------------------------------------------------------------- scratch
__device__ float g_h [2][NN * 128];
__device__ float g_hs[2][NN * 128];
__device__ int   g_cnt[2][NN];                 // fill cursor == final degree
__device__ float g_dis[2][NN];                 // rsqrt(deg+1)
__device__ int   g_adj[2][NN * ADJ_STRIDE];
// B fragments in mma register order: [mtx][kc(8)][ntile(16)][split hi/lo][lane(32)][2 regs]
__device__ u32 g_Bfrag[3][8][16][2][32][2];

// ---------------------------------------------------------------- helpers
__device__ __forceinline__ u32 smem_u32(const void* p) {
    u32 a;
    asm("{ .reg .u64 t; cvta.to.shared.u64 t, %1; cvt.u32.u64 %0, t; }"
        : "=r"(a) : "l"(p));
    return a;
}
__device__ __forceinline__ void mma_bf16(float* c, const u32* a, u32 b0, u32 b1) {
    asm volatile(
        "mma.sync.aligned.m16n8k16.row.col.f32.bf16.bf16.f32 "
        "{%0,%1,%2,%3}, {%4,%5,%6,%7}, {%8,%9}, {%0,%1,%2,%3};"
        : "+f"(c[0]), "+f"(c[1]), "+f"(c[2]), "+f"(c[3])
        : "r"(a[0]), "r"(a[1]), "r"(a[2]), "r"(a[3]), "r"(b0), "r"(b1));
}
__device__ __forceinline__ void ldsm4(u32* r, u32 addr) {
    asm volatile(
        "ldmatrix.sync.aligned.m8n8.x4.shared.b16 {%0,%1,%2,%3}, [%4];"
        : "=r"(r[0]), "=r"(r[1]), "=r"(r[2]), "=r"(r[3]) : "r"(addr));
}
__device__ __forceinline__ u32 pack_bf16(float a, float b) {
    __nv_bfloat162 p = make_bfloat162(__float2bfloat16(a), __float2bfloat16(b));
    return *(u32*)&p;
}

// ---------------------------------------------------------------- prep
// Zero degree counters + build B fragment images.
__global__ void prep_kernel(const float* __restrict__ W1,
                            const float* __restrict__ W2,
                            const float* __restrict__ W3, int n) {
    int idx = blockIdx.x * 256 + threadIdx.x;
    if (idx < n) { g_cnt[0][idx] = 0; g_cnt[1][idx] = 0; }
    if (idx < 3 * 8192) {
        int lane  = idx & 31;
        int split = (idx >> 5) & 1;
        int nt    = (idx >> 6) & 15;
        int kc    = (idx >> 10) & 7;
        int mtx   = idx >> 13;
        int outc  = (mtx == 2) ? 64 : 128;
        if (nt * 8 < outc) {
            const float* W = (mtx == 0) ? W1 : ((mtx == 1) ? W2 : W3);
            int c  = nt * 8 + (lane >> 2);
            int k0 = kc * 16 + (lane & 3) * 2;
#pragma unroll
            for (int r = 0; r < 2; r++) {
                int k = k0 + 8 * r;
                float w0 = W[k * outc + c];
                float w1 = W[(k + 1) * outc + c];
                u32 val;
                if (split == 0) {
                    val = pack_bf16(w0, w1);
                } else {
                    float h0 = __bfloat162float(__float2bfloat16(w0));
                    float h1 = __bfloat162float(__float2bfloat16(w1));
                    val = pack_bf16(w0 - h0, w1 - h1);
                }
                g_Bfrag[mtx][kc][nt][split][lane][r] = val;
            }
        }
    }
}

// ---------------------------------------------------------------- adjacency
// One pass: bucketed adjacency build (no scan needed).
__global__ void fill_kernel(const int* __restrict__ se,
                            const int* __restrict__ te, int m) {
    int net = blockIdx.y;
    const int* src = net ? te : se;
    const int* dst = src + m;
    int* cnt = g_cnt[net];
    int* adj = g_adj[net];
    for (int e = blockIdx.x * blockDim.x + threadIdx.x; e < m;
         e += gridDim.x * blockDim.x) {
        int d = dst[e];
        int p = atomicAdd(&cnt[d], 1);
        if (p < ADJ_STRIDE) adj[d * ADJ_STRIDE + p] = src[e];
    }
}

// deg -> dis (after fill)
__global__ void dis_kernel(int n) {
    int net = blockIdx.y;
    int i = blockIdx.x * blockDim.x + threadIdx.x;
    if (i < n) g_dis[net][i] = rsqrtf((float)(g_cnt[net][i] + 1));
}

// ---------------------------------------------------------------- mma GEMM
// g_h[net][r,:] = (relu?)X[r,:] @ W   (R11 winner form: occ 3, no sw pipeline)
template <int OUTC, bool RELU_IN>
__global__ void __launch_bounds__(256, 3)
gemm_mma_kernel(const float* __restrict__ X0, const float* __restrict__ X1,
                int midx0, int midx1, int n) {
    constexpr int PA = 136;
    constexpr int WCOLS = OUTC / 4;
    constexpr int NTILE = WCOLS / 8;
    constexpr int A_SPLIT = 64 * PA * 2;

    extern __shared__ char smem[];
    __nv_bfloat16* sAhi = (__nv_bfloat16*)smem;
    __nv_bfloat16* sAlo = (__nv_bfloat16*)(smem + A_SPLIT);

    int tid = threadIdx.x;
    int net = blockIdx.y;
    const float* X = net ? X1 : X0;
    int midx = net ? midx1 : midx0;
    int row0 = blockIdx.x * 64;
    float* H = g_h[net];

    // stage X -> bf16 hi/lo
    {
        int r = tid >> 2;
        int c0 = (tid & 3) * 32;
        int gr = row0 + r;
        const float4* xrow = (const float4*)(X + (size_t)gr * 128 + c0);
        u32* ah = (u32*)&sAhi[r * PA + c0];
        u32* al = (u32*)&sAlo[r * PA + c0];
#pragma unroll
        for (int j = 0; j < 8; j++) {
            float4 v = make_float4(0.f, 0.f, 0.f, 0.f);
            if (gr < n) v = xrow[j];
            if (RELU_IN) {
                v.x = fmaxf(v.x, 0.f); v.y = fmaxf(v.y, 0.f);
                v.z = fmaxf(v.z, 0.f); v.w = fmaxf(v.w, 0.f);
            }
            float hx = __bfloat162float(__float2bfloat16(v.x));
            float hy = __bfloat162float(__float2bfloat16(v.y));
            float hz = __bfloat162float(__float2bfloat16(v.z));
            float hw = __bfloat162float(__float2bfloat16(v.w));
            ah[2 * j]     = pack_bf16(v.x, v.y);
            ah[2 * j + 1] = pack_bf16(v.z, v.w);
            al[2 * j]     = pack_bf16(v.x - hx, v.y - hy);
            al[2 * j + 1] = pack_bf16(v.z - hz, v.w - hw);
        }
    }
    __syncthreads();

    int lane = tid & 31, w = tid >> 5;
    int rowg = w >> 2, colg = w & 3;

    u32 sAhi_u = smem_u32(sAhi), sAlo_u = smem_u32(sAlo);
    u32 aoff = ((rowg * 32 + (lane & 15)) * PA + ((lane >> 4) << 3)) * 2;

    const uint2* bfr = (const uint2*)g_Bfrag[midx];

    float acc[NTILE][2][4];
#pragma unroll
    for (int t = 0; t < NTILE; t++)
#pragma unroll
        for (int fr = 0; fr < 2; fr++)
#pragma unroll
            for (int i = 0; i < 4; i++) acc[t][fr][i] = 0.f;

#pragma unroll
    for (int kc = 0; kc < 8; kc++) {
        uint2 bh[NTILE], bl[NTILE];
#pragma unroll
        for (int t = 0; t < NTILE; t++) {
            int ntg = colg * NTILE + t;
            bh[t] = __ldg(&bfr[((kc * 16 + ntg) * 2 + 0) * 32 + lane]);
            bl[t] = __ldg(&bfr[((kc * 16 + ntg) * 2 + 1) * 32 + lane]);
        }
        u32 ah[2][4], al[2][4];
#pragma unroll
        for (int fr = 0; fr < 2; fr++) {
            ldsm4(ah[fr], sAhi_u + aoff + fr * (16 * PA * 2) + kc * 32);
            ldsm4(al[fr], sAlo_u + aoff + fr * (16 * PA * 2) + kc * 32);
        }
#pragma unroll
        for (int t = 0; t < NTILE; t++)
#pragma unroll
            for (int fr = 0; fr < 2; fr++) {
                mma_bf16(acc[t][fr], ah[fr], bh[t].x, bh[t].y);
                mma_bf16(acc[t][fr], al[fr], bh[t].x, bh[t].y);
                mma_bf16(acc[t][fr], ah[fr], bl[t].x, bl[t].y);
            }
    }

    {
        int qrow = lane >> 2, qk = (lane & 3) * 2;
#pragma unroll
        for (int fr = 0; fr < 2; fr++) {
            int gr0 = row0 + rowg * 32 + fr * 16 + qrow;
            int gr1 = gr0 + 8;
#pragma unroll
            for (int t = 0; t < NTILE; t++) {
                int col = colg * WCOLS + t * 8 + qk;
                if (gr0 < n) {
                    float2 v = make_float2(acc[t][fr][0], acc[t][fr][1]);
                    *(float2*)&H[(size_t)gr0 * OUTC + col] = v;
                }
                if (gr1 < n) {
                    float2 v = make_float2(acc[t][fr][2], acc[t][fr][3]);
                    *(float2*)&H[(size_t)gr1 * OUTC + col] = v;
                }
            }
        }
    }
}

// ---------------------------------------------------------------- aggregation
// out[w] = dis[w]*(h[w]*dis[w] + sum_s h[s]*dis[s]) + bias
// ONE net per launch -> working set (H 51MB + adj 16MB) fits L2.
__global__ void agg128_kernel(const float* __restrict__ bias, int net, int n) {
    int w = (blockIdx.x * blockDim.x + threadIdx.x) >> 5;
    int lane = threadIdx.x & 31;
    if (w >= n) return;
    const float4* H4 = (const float4*)g_h[net];
    const float* dis = g_dis[net];
    const int* adj = g_adj[net] + (size_t)w * ADJ_STRIDE;
    int deg = g_cnt[net][w];
    float dw = dis[w];
    float4 self = H4[(size_t)w * 32 + lane];
    float4 acc = make_float4(self.x * dw, self.y * dw, self.z * dw, self.w * dw);
    int j = 0;
    for (; j + 4 <= deg; j += 4) {
        int s0 = adj[j], s1 = adj[j + 1], s2 = adj[j + 2], s3 = adj[j + 3];
        float4 v0 = H4[(size_t)s0 * 32 + lane];
        float4 v1 = H4[(size_t)s1 * 32 + lane];
        float4 v2 = H4[(size_t)s2 * 32 + lane];
        float4 v3 = H4[(size_t)s3 * 32 + lane];
        float d0 = dis[s0], d1 = dis[s1], d2 = dis[s2], d3 = dis[s3];
        acc.x += v0.x * d0 + v1.x * d1 + v2.x * d2 + v3.x * d3;
        acc.y += v0.y * d0 + v1.y * d1 + v2.y * d2 + v3.y * d3;
        acc.z += v0.z * d0 + v1.z * d1 + v2.z * d2 + v3.z * d3;
        acc.w += v0.w * d0 + v1.w * d1 + v2.w * d2 + v3.w * d3;
    }
    for (; j < deg; j++) {
        int s = adj[j];
        float dsn = dis[s];
        float4 v = H4[(size_t)s * 32 + lane];
        acc.x += v.x * dsn; acc.y += v.y * dsn;
        acc.z += v.z * dsn; acc.w += v.w * dsn;
    }
    float4 bb = ((const float4*)bias)[lane];
    acc.x = acc.x * dw + bb.x;
    acc.y = acc.y * dw + bb.y;
    acc.z = acc.z * dw + bb.z;
    acc.w = acc.w * dw + bb.w;
    ((float4*)g_hs[net])[(size_t)w * 32 + lane] = acc;
}

__global__ void agg64_kernel(const float* __restrict__ bias,
                             float* __restrict__ Out, int net, int n) {
    int w = (blockIdx.x * blockDim.x + threadIdx.x) >> 5;
    int lane = threadIdx.x & 31;
    if (w >= n) return;
    const float2* H2 = (const float2*)g_h[net];
    const float* dis = g_dis[net];
    const int* adj = g_adj[net] + (size_t)w * ADJ_STRIDE;
    int deg = g_cnt[net][w];
    float dw = dis[w];
    float2 self = H2[(size_t)w * 32 + lane];
    float2 acc = make_float2(self.x * dw, self.y * dw);
    int j = 0;
    for (; j + 4 <= deg; j += 4) {
        int s0 = adj[j], s1 = adj[j + 1], s2 = adj[j + 2], s3 = adj[j + 3];
        float2 v0 = H2[(size_t)s0 * 32 + lane];
        float2 v1 = H2[(size_t)s1 * 32 + lane];
        float2 v2 = H2[(size_t)s2 * 32 + lane];
        float2 v3 = H2[(size_t)s3 * 32 + lane];
        float d0 = dis[s0], d1 = dis[s1], d2 = dis[s2], d3 = dis[s3];
        acc.x += v0.x * d0 + v1.x * d1 + v2.x * d2 + v3.x * d3;
        acc.y += v0.y * d0 + v1.y * d1 + v2.y * d2 + v3.y * d3;
    }
    for (; j < deg; j++) {
        int s = adj[j];
        float dsn = dis[s];
        float2 v = H2[(size_t)s * 32 + lane];
        acc.x += v.x * dsn;
        acc.y += v.y * dsn;
    }
    float2 bb = ((const float2*)bias)[lane];
    acc.x = acc.x * dw + bb.x;
    acc.y = acc.y * dw + bb.y;
    ((float2*)Out)[(size_t)w * 32 + lane] = acc;
}

// ---------------------------------------------------------------- decoder
__global__ void decoder_kernel(const float* __restrict__ zs,
                               const float* __restrict__ zt,
                               const int* __restrict__ se,
                               const int* __restrict__ te,
                               float* __restrict__ P, int m) {
    int gid = blockIdx.x * blockDim.x + threadIdx.x;
    int e = gid >> 4;
    int l = gid & 15;
    int ec = min(e, 2 * m - 1);
    int net = (ec >= m);
    int el = net ? (ec - m) : ec;
    const int* ea = net ? te : se;
    const float* Z = net ? zt : zs;
    int a = ea[el], b = ea[el + m];
    const float4* Z4 = (const float4*)Z;
    float4 va = Z4[(size_t)a * 16 + l];
    float4 vb = Z4[(size_t)b * 16 + l];
    float s = va.x * vb.x + va.y * vb.y + va.z * vb.z + va.w * vb.w;
    s += __shfl_xor_sync(0xffffffffu, s, 8);
    s += __shfl_xor_sync(0xffffffffu, s, 4);
    s += __shfl_xor_sync(0xffffffffu, s, 2);
    s += __shfl_xor_sync(0xffffffffu, s, 1);
    if (l == 0 && e < 2 * m) P[e] = 1.0f / (1.0f + expf(-s));
}

// ---------------------------------------------------------------- launch
extern "C" void kernel_launch(void* const* d_in, const int* in_sizes, int n_in,
                              void* d_out, int out_size) {
    const float* xs = (const float*)d_in[0];
    const float* xt = (const float*)d_in[1];
    const int*   se = (const int*)d_in[2];
    const int*   te = (const int*)d_in[3];
    const float* W1 = (const float*)d_in[4];
    const float* b1 = (const float*)d_in[5];
    const float* W2 = (const float*)d_in[6];
    const float* b2 = (const float*)d_in[7];
    const float* W3 = (const float*)d_in[8];
    const float* b3 = (const float*)d_in[9];

    int n = in_sizes[0] / 128;   // 100000
    int m = in_sizes[2] / 2;     // 500000

    float* out = (float*)d_out;
    float* zs = out;
    float* zt = out + (size_t)n * 64;
    float* ps = zt + (size_t)n * 64;

    float *hsbuf;
    cudaGetSymbolAddress((void**)&hsbuf, g_hs);

    const int SMA = 2 * (64 * 136 * 2);   // 34816 bytes (A hi+lo only)
    cudaFuncSetAttribute(gemm_mma_kernel<128, false>,
                         cudaFuncAttributeMaxDynamicSharedMemorySize, SMA);
    cudaFuncSetAttribute(gemm_mma_kernel<64, true>,
                         cudaFuncAttributeMaxDynamicSharedMemorySize, SMA);

    dim3 gm512((m + 511) / 512, 2);
    dim3 gn256((n + 255) / 256, 2);
    dim3 gtc((n + 63) / 64, 2);
    int gb_agg = (n + 7) / 8;
    int gb_dec = (2 * m + 15) / 16;

    prep_kernel<<<(n + 255) / 256, 256>>>(W1, W2, W3, n);              // 0
    fill_kernel<<<gm512, 512>>>(se, te, m);                            // 1
    gemm_mma_kernel<128, false><<<gtc, 256, SMA>>>(xs, xt, 0, 1, n);   // 2
    dis_kernel<<<gn256, 256>>>(n);                                     // 3
    agg128_kernel<<<gb_agg, 256>>>(b1, 0, n);                          // 4
    agg128_kernel<<<gb_agg, 256>>>(b2, 1, n);                          // 5
    gemm_mma_kernel<64, true><<<gtc, 256, SMA>>>(hsbuf,
                                                 hsbuf + (size_t)NN * 128,
                                                 2, 2, n);             // 6
    agg64_kernel<<<gb_agg, 256>>>(b3, zs, 0, n);                       // 7
    agg64_kernel<<<gb_agg, 256>>>(b3, zt, 1, n);                       // 8
    decoder_kernel<<<gb_dec, 256>>>(zs, zt, se, te, ps, m);            // 9
}

// round 16
// speedup vs baseline: 1.0742x; 1.0742x over previous
#include <cuda_runtime.h>
#include <cuda_bf16.h>
#include <math.h>
#include <cstdint>

#define NN 100000
#define EE 500000
#define NB_MAX 128   // ceil(NN/1024) = 98 <= 128

typedef unsigned int u32;

// ---------------------------------------------------------------- scratch
__device__ float g_h [2][NN * 128];
__device__ float g_hs[2][NN * 128];
__device__ int   g_cnt[2][NN];
__device__ int   g_off[2][NN + 1];
__device__ int   g_cur[2][NN];
__device__ int   g_adj[2][EE];
__device__ float g_dis[2][NN];   // rsqrt(deg)
__device__ int   g_bsum[2][NB_MAX];
__device__ int   g_bpre[2][NB_MAX];
// B fragments in mma register order: [mtx][kc(8)][ntile(16)][split hi/lo][lane(32)][2 regs]
__device__ u32 g_Bfrag[3][8][16][2][32][2];

// ---------------------------------------------------------------- helpers
__device__ __forceinline__ u32 smem_u32(const void* p) {
    u32 a;
    asm("{ .reg .u64 t; cvta.to.shared.u64 t, %1; cvt.u32.u64 %0, t; }"
        : "=r"(a) : "l"(p));
    return a;
}
__device__ __forceinline__ void mma_bf16(float* c, const u32* a, u32 b0, u32 b1) {
    asm volatile(
        "mma.sync.aligned.m16n8k16.row.col.f32.bf16.bf16.f32 "
        "{%0,%1,%2,%3}, {%4,%5,%6,%7}, {%8,%9}, {%0,%1,%2,%3};"
        : "+f"(c[0]), "+f"(c[1]), "+f"(c[2]), "+f"(c[3])
        : "r"(a[0]), "r"(a[1]), "r"(a[2]), "r"(a[3]), "r"(b0), "r"(b1));
}
__device__ __forceinline__ void ldsm4(u32* r, u32 addr) {
    asm volatile(
        "ldmatrix.sync.aligned.m8n8.x4.shared.b16 {%0,%1,%2,%3}, [%4];"
        : "=r"(r[0]), "=r"(r[1]), "=r"(r[2]), "=r"(r[3]) : "r"(addr));
}
__device__ __forceinline__ u32 pack_bf16(float a, float b) {
    __nv_bfloat162 p = make_bfloat162(__float2bfloat16(a), __float2bfloat16(b));
    return *(u32*)&p;
}

// ---------------------------------------------------------------- prep
__global__ void prep_kernel(const float* __restrict__ W1,
                            const float* __restrict__ W2,
                            const float* __restrict__ W3, int n) {
    int idx = blockIdx.x * 256 + threadIdx.x;
    if (idx < n) { g_cnt[0][idx] = 0; g_cnt[1][idx] = 0; }
    if (idx < 3 * 8192) {
        int lane  = idx & 31;
        int split = (idx >> 5) & 1;
        int nt    = (idx >> 6) & 15;
        int kc    = (idx >> 10) & 7;
        int mtx   = idx >> 13;
        int outc  = (mtx == 2) ? 64 : 128;
        if (nt * 8 < outc) {
            const float* W = (mtx == 0) ? W1 : ((mtx == 1) ? W2 : W3);
            int c  = nt * 8 + (lane >> 2);
            int k0 = kc * 16 + (lane & 3) * 2;
#pragma unroll
            for (int r = 0; r < 2; r++) {
                int k = k0 + 8 * r;
                float w0 = W[k * outc + c];
                float w1 = W[(k + 1) * outc + c];
                u32 val;
                if (split == 0) {
                    val = pack_bf16(w0, w1);
                } else {
                    float h0 = __bfloat162float(__float2bfloat16(w0));
                    float h1 = __bfloat162float(__float2bfloat16(w1));
                    val = pack_bf16(w0 - h0, w1 - h1);
                }
                g_Bfrag[mtx][kc][nt][split][lane][r] = val;
            }
        }
    }
}

// ---------------------------------------------------------------- CSR build
__global__ void count_kernel(const int* __restrict__ se,
                             const int* __restrict__ te, int m) {
    int net = blockIdx.y;
    const int* dst = (net ? te : se) + m;
    for (int e = blockIdx.x * blockDim.x + threadIdx.x; e < m;
         e += gridDim.x * blockDim.x)
        atomicAdd(&g_cnt[net][dst[e]], 1);
}

__global__ void scanA_kernel(int n) {
    __shared__ int ss[1024];
    int net = blockIdx.y;
    int t = threadIdx.x;
    int i = blockIdx.x * 1024 + t;
    int c = (i < n) ? g_cnt[net][i] : 0;
    ss[t] = c;
    __syncthreads();
    for (int d = 1; d < 1024; d <<= 1) {
        int v = (t >= d) ? ss[t - d] : 0;
        __syncthreads();
        ss[t] += v;
        __syncthreads();
    }
    if (i < n) {
        g_off[net][i] = ss[t] - c;
        g_dis[net][i] = rsqrtf((float)(c + 1));
    }
    if (t == 1023) g_bsum[net][blockIdx.x] = ss[1023];
}

__global__ void scanB_kernel(int nb, int n) {
    __shared__ int ss[NB_MAX];
    int net = blockIdx.y;
    int t = threadIdx.x;
    int c = (t < nb) ? g_bsum[net][t] : 0;
    ss[t] = c;
    __syncthreads();
    for (int d = 1; d < NB_MAX; d <<= 1) {
        int v = (t >= d) ? ss[t - d] : 0;
        __syncthreads();
        ss[t] += v;
        __syncthreads();
    }
    if (t < nb) g_bpre[net][t] = ss[t] - c;
    if (t == NB_MAX - 1) g_off[net][n] = ss[NB_MAX - 1];
}

__global__ void scanC_kernel(int n) {
    int net = blockIdx.y;
    int i = blockIdx.x * 1024 + threadIdx.x;
    if (i < n) {
        int v = g_off[net][i] + g_bpre[net][i >> 10];
        g_off[net][i] = v;
        g_cur[net][i] = v;
    }
}

__global__ void fill_kernel(const int* __restrict__ se,
                            const int* __restrict__ te, int m) {
    int net = blockIdx.y;
    const int* src = net ? te : se;
    const int* dst = src + m;
    for (int e = blockIdx.x * blockDim.x + threadIdx.x; e < m;
         e += gridDim.x * blockDim.x) {
        int p = atomicAdd(&g_cur[net][dst[e]], 1);
        g_adj[net][p] = src[e];
    }
}

// ---------------------------------------------------------------- mma GEMM
// g_h[net][r,:] = (relu?)X[r,:] @ W   (R11 winner form: occ 3, no sw pipeline)
template <int OUTC, bool RELU_IN>
__global__ void __launch_bounds__(256, 3)
gemm_mma_kernel(const float* __restrict__ X0, const float* __restrict__ X1,
                int midx0, int midx1, int n) {
    constexpr int PA = 136;
    constexpr int WCOLS = OUTC / 4;
    constexpr int NTILE = WCOLS / 8;
    constexpr int A_SPLIT = 64 * PA * 2;

    extern __shared__ char smem[];
    __nv_bfloat16* sAhi = (__nv_bfloat16*)smem;
    __nv_bfloat16* sAlo = (__nv_bfloat16*)(smem + A_SPLIT);

    int tid = threadIdx.x;
    int net = blockIdx.y;
    const float* X = net ? X1 : X0;
    int midx = net ? midx1 : midx0;
    int row0 = blockIdx.x * 64;
    float* H = g_h[net];

    // stage X -> bf16 hi/lo
    {
        int r = tid >> 2;
        int c0 = (tid & 3) * 32;
        int gr = row0 + r;
        const float4* xrow = (const float4*)(X + (size_t)gr * 128 + c0);
        u32* ah = (u32*)&sAhi[r * PA + c0];
        u32* al = (u32*)&sAlo[r * PA + c0];
#pragma unroll
        for (int j = 0; j < 8; j++) {
            float4 v = make_float4(0.f, 0.f, 0.f, 0.f);
            if (gr < n) v = xrow[j];
            if (RELU_IN) {
                v.x = fmaxf(v.x, 0.f); v.y = fmaxf(v.y, 0.f);
                v.z = fmaxf(v.z, 0.f); v.w = fmaxf(v.w, 0.f);
            }
            float hx = __bfloat162float(__float2bfloat16(v.x));
            float hy = __bfloat162float(__float2bfloat16(v.y));
            float hz = __bfloat162float(__float2bfloat16(v.z));
            float hw = __bfloat162float(__float2bfloat16(v.w));
            ah[2 * j]     = pack_bf16(v.x, v.y);
            ah[2 * j + 1] = pack_bf16(v.z, v.w);
            al[2 * j]     = pack_bf16(v.x - hx, v.y - hy);
            al[2 * j + 1] = pack_bf16(v.z - hz, v.w - hw);
        }
    }
    __syncthreads();

    int lane = tid & 31, w = tid >> 5;
    int rowg = w >> 2, colg = w & 3;

    u32 sAhi_u = smem_u32(sAhi), sAlo_u = smem_u32(sAlo);
    u32 aoff = ((rowg * 32 + (lane & 15)) * PA + ((lane >> 4) << 3)) * 2;

    const uint2* bfr = (const uint2*)g_Bfrag[midx];

    float acc[NTILE][2][4];
#pragma unroll
    for (int t = 0; t < NTILE; t++)
#pragma unroll
        for (int fr = 0; fr < 2; fr++)
#pragma unroll
            for (int i = 0; i < 4; i++) acc[t][fr][i] = 0.f;

#pragma unroll
    for (int kc = 0; kc < 8; kc++) {
        uint2 bh[NTILE], bl[NTILE];
#pragma unroll
        for (int t = 0; t < NTILE; t++) {
            int ntg = colg * NTILE + t;
            bh[t] = __ldg(&bfr[((kc * 16 + ntg) * 2 + 0) * 32 + lane]);
            bl[t] = __ldg(&bfr[((kc * 16 + ntg) * 2 + 1) * 32 + lane]);
        }
        u32 ah[2][4], al[2][4];
#pragma unroll
        for (int fr = 0; fr < 2; fr++) {
            ldsm4(ah[fr], sAhi_u + aoff + fr * (16 * PA * 2) + kc * 32);
            ldsm4(al[fr], sAlo_u + aoff + fr * (16 * PA * 2) + kc * 32);
        }
#pragma unroll
        for (int t = 0; t < NTILE; t++)
#pragma unroll
            for (int fr = 0; fr < 2; fr++) {
                mma_bf16(acc[t][fr], ah[fr], bh[t].x, bh[t].y);
                mma_bf16(acc[t][fr], al[fr], bh[t].x, bh[t].y);
                mma_bf16(acc[t][fr], ah[fr], bl[t].x, bl[t].y);
            }
    }

    {
        int qrow = lane >> 2, qk = (lane & 3) * 2;
#pragma unroll
        for (int fr = 0; fr < 2; fr++) {
            int gr0 = row0 + rowg * 32 + fr * 16 + qrow;
            int gr1 = gr0 + 8;
#pragma unroll
            for (int t = 0; t < NTILE; t++) {
                int col = colg * WCOLS + t * 8 + qk;
                if (gr0 < n) {
                    float2 v = make_float2(acc[t][fr][0], acc[t][fr][1]);
                    *(float2*)&H[(size_t)gr0 * OUTC + col] = v;
                }
                if (gr1 < n) {
                    float2 v = make_float2(acc[t][fr][2], acc[t][fr][3]);
                    *(float2*)&H[(size_t)gr1 * OUTC + col] = v;
                }
            }
        }
    }
}

// ---------------------------------------------------------------- aggregation
// out[w] = dis[w]*(h[w]*dis[w] + sum_s h[s]*dis[s]) + bias    (4-way MLP)
__global__ void agg128_kernel(const float* __restrict__ b1,
                              const float* __restrict__ b2, int n) {
    int net = blockIdx.y;
    int w = (blockIdx.x * blockDim.x + threadIdx.x) >> 5;
    int lane = threadIdx.x & 31;
    if (w >= n) return;
    const float4* H4 = (const float4*)g_h[net];
    const float* bias = net ? b2 : b1;
    const float* dis = g_dis[net];
    float dw = dis[w];
    float4 self = H4[(size_t)w * 32 + lane];
    float4 acc = make_float4(self.x * dw, self.y * dw, self.z * dw, self.w * dw);
    int j = g_off[net][w], e0 = g_off[net][w + 1];
    const int* adj = g_adj[net];
    for (; j + 4 <= e0; j += 4) {
        int s0 = __ldg(&adj[j]), s1 = __ldg(&adj[j + 1]);
        int s2 = __ldg(&adj[j + 2]), s3 = __ldg(&adj[j + 3]);
        float4 v0 = H4[(size_t)s0 * 32 + lane];
        float4 v1 = H4[(size_t)s1 * 32 + lane];
        float4 v2 = H4[(size_t)s2 * 32 + lane];
        float4 v3 = H4[(size_t)s3 * 32 + lane];
        float d0 = __ldg(&dis[s0]), d1 = __ldg(&dis[s1]);
        float d2 = __ldg(&dis[s2]), d3 = __ldg(&dis[s3]);
        acc.x += v0.x * d0 + v1.x * d1 + v2.x * d2 + v3.x * d3;
        acc.y += v0.y * d0 + v1.y * d1 + v2.y * d2 + v3.y * d3;
        acc.z += v0.z * d0 + v1.z * d1 + v2.z * d2 + v3.z * d3;
        acc.w += v0.w * d0 + v1.w * d1 + v2.w * d2 + v3.w * d3;
    }
    for (; j < e0; j++) {
        int s = __ldg(&adj[j]);
        float dsn = __ldg(&dis[s]);
        float4 v = H4[(size_t)s * 32 + lane];
        acc.x += v.x * dsn; acc.y += v.y * dsn;
        acc.z += v.z * dsn; acc.w += v.w * dsn;
    }
    float4 bb = ((const float4*)bias)[lane];
    acc.x = acc.x * dw + bb.x;
    acc.y = acc.y * dw + bb.y;
    acc.z = acc.z * dw + bb.z;
    acc.w = acc.w * dw + bb.w;
    ((float4*)g_hs[net])[(size_t)w * 32 + lane] = acc;
}

__global__ void agg64_kernel(const float* __restrict__ bias,
                             float* __restrict__ zs,
                             float* __restrict__ zt, int n) {
    int net = blockIdx.y;
    int w = (blockIdx.x * blockDim.x + threadIdx.x) >> 5;
    int lane = threadIdx.x & 31;
    if (w >= n) return;
    const float2* H2 = (const float2*)g_h[net];
    const float* dis = g_dis[net];
    float dw = dis[w];
    float2 self = H2[(size_t)w * 32 + lane];
    float2 acc = make_float2(self.x * dw, self.y * dw);
    int j = g_off[net][w], e0 = g_off[net][w + 1];
    const int* adj = g_adj[net];
    for (; j + 4 <= e0; j += 4) {
        int s0 = __ldg(&adj[j]), s1 = __ldg(&adj[j + 1]);
        int s2 = __ldg(&adj[j + 2]), s3 = __ldg(&adj[j + 3]);
        float2 v0 = H2[(size_t)s0 * 32 + lane];
        float2 v1 = H2[(size_t)s1 * 32 + lane];
        float2 v2 = H2[(size_t)s2 * 32 + lane];
        float2 v3 = H2[(size_t)s3 * 32 + lane];
        float d0 = __ldg(&dis[s0]), d1 = __ldg(&dis[s1]);
        float d2 = __ldg(&dis[s2]), d3 = __ldg(&dis[s3]);
        acc.x += v0.x * d0 + v1.x * d1 + v2.x * d2 + v3.x * d3;
        acc.y += v0.y * d0 + v1.y * d1 + v2.y * d2 + v3.y * d3;
    }
    for (; j < e0; j++) {
        int s = __ldg(&adj[j]);
        float dsn = __ldg(&dis[s]);
        float2 v = H2[(size_t)s * 32 + lane];
        acc.x += v.x * dsn;
        acc.y += v.y * dsn;
    }
    float2 bb = ((const float2*)bias)[lane];
    acc.x = acc.x * dw + bb.x;
    acc.y = acc.y * dw + bb.y;
    float* Out = net ? zt : zs;
    ((float2*)Out)[(size_t)w * 32 + lane] = acc;
}

// ---------------------------------------------------------------- decoder
__global__ void decoder_kernel(const float* __restrict__ zs,
                               const float* __restrict__ zt,
                               const int* __restrict__ se,
                               const int* __restrict__ te,
                               float* __restrict__ P, int m) {
    int gid = blockIdx.x * blockDim.x + threadIdx.x;
    int e = gid >> 4;
    int l = gid & 15;
    int ec = min(e, 2 * m - 1);
    int net = (ec >= m);
    int el = net ? (ec - m) : ec;
    const int* ea = net ? te : se;
    const float* Z = net ? zt : zs;
    int a = ea[el], b = ea[el + m];
    const float4* Z4 = (const float4*)Z;
    float4 va = Z4[(size_t)a * 16 + l];
    float4 vb = Z4[(size_t)b * 16 + l];
    float s = va.x * vb.x + va.y * vb.y + va.z * vb.z + va.w * vb.w;
    s += __shfl_xor_sync(0xffffffffu, s, 8);
    s += __shfl_xor_sync(0xffffffffu, s, 4);
    s += __shfl_xor_sync(0xffffffffu, s, 2);
    s += __shfl_xor_sync(0xffffffffu, s, 1);
    if (l == 0 && e < 2 * m) P[e] = 1.0f / (1.0f + expf(-s));
}

// ---------------------------------------------------------------- launch
extern "C" void kernel_launch(void* const* d_in, const int* in_sizes, int n_in,
                              void* d_out, int out_size) {
    const float* xs = (const float*)d_in[0];
    const float* xt = (const float*)d_in[1];
    const int*   se = (const int*)d_in[2];
    const int*   te = (const int*)d_in[3];
    const float* W1 = (const float*)d_in[4];
    const float* b1 = (const float*)d_in[5];
    const float* W2 = (const float*)d_in[6];
    const float* b2 = (const float*)d_in[7];
    const float* W3 = (const float*)d_in[8];
    const float* b3 = (const float*)d_in[9];

    int n = in_sizes[0] / 128;   // 100000
    int m = in_sizes[2] / 2;     // 500000

    float* out = (float*)d_out;
    float* zs = out;
    float* zt = out + (size_t)n * 64;
    float* ps = zt + (size_t)n * 64;

    float *hsbuf;
    cudaGetSymbolAddress((void**)&hsbuf, g_hs);

    const int SMA = 2 * (64 * 136 * 2);   // 34816 bytes (A hi+lo only)
    cudaFuncSetAttribute(gemm_mma_kernel<128, false>,
                         cudaFuncAttributeMaxDynamicSharedMemorySize, SMA);
    cudaFuncSetAttribute(gemm_mma_kernel<64, true>,
                         cudaFuncAttributeMaxDynamicSharedMemorySize, SMA);

    int nb = (n + 1023) / 1024;  // 98
    dim3 gm512((m + 511) / 512, 2);
    dim3 gscan(nb, 2);
    dim3 gone(1, 2);
    dim3 gtc((n + 63) / 64, 2);
    dim3 gagg((n + 7) / 8, 2);
    int gb_dec = (2 * m + 15) / 16;

    // Side stream + fork/join events (R12 topology — passed mem-guard twice).
    cudaStream_t s2;
    cudaStreamCreateWithFlags(&s2, cudaStreamNonBlocking);
    cudaEvent_t ev1, ev2;
    cudaEventCreateWithFlags(&ev1, cudaEventDisableTiming);
    cudaEventCreateWithFlags(&ev2, cudaEventDisableTiming);

    // prep: Bfrag + zeroed counters
    prep_kernel<<<(n + 255) / 256, 256>>>(W1, W2, W3, n);
    cudaEventRecord(ev1, 0);
    cudaStreamWaitEvent(s2, ev1, 0);

    // CSR chain on side stream, overlapped with gemm128 on main stream
    count_kernel<<<gm512, 512, 0, s2>>>(se, te, m);
    scanA_kernel<<<gscan, 1024, 0, s2>>>(n);
    gemm_mma_kernel<128, false><<<gtc, 256, SMA>>>(xs, xt, 0, 1, n);
    scanB_kernel<<<gone, NB_MAX, 0, s2>>>(nb, n);
    scanC_kernel<<<gscan, 1024, 0, s2>>>(n);
    fill_kernel<<<gm512, 512, 0, s2>>>(se, te, m);
    cudaEventRecord(ev2, s2);
    cudaStreamWaitEvent(0, ev2, 0);

    agg128_kernel<<<gagg, 256>>>(b1, b2, n);
    gemm_mma_kernel<64, true><<<gtc, 256, SMA>>>(hsbuf,
                                                 hsbuf + (size_t)NN * 128,
                                                 2, 2, n);
    agg64_kernel<<<gagg, 256>>>(b3, zs, zt, n);
    decoder_kernel<<<gb_dec, 256>>>(zs, zt, se, te, ps, m);
}

// round 17
// speedup vs baseline: 1.0899x; 1.0146x over previous
#include <cuda_runtime.h>
#include <cuda_bf16.h>
#include <math.h>
#include <cstdint>

#define NN 100000
#define EE 500000
#define NB_MAX 128   // ceil(NN/1024) = 98 <= 128

typedef unsigned int u32;

// ---------------------------------------------------------------- scratch
__device__ float g_h [2][NN * 128];
__device__ float g_hs[2][NN * 128];
__device__ int   g_cnt[2][NN];
__device__ int   g_off[2][NN + 1];
__device__ int   g_cur[2][NN];
__device__ int   g_adj[2][EE];
__device__ float g_dis[2][NN];   // rsqrt(deg)
__device__ int   g_bsum[2][NB_MAX];
__device__ int   g_bpre[2][NB_MAX];
// B fragments in mma register order: [mtx][kc(8)][ntile(16)][split hi/lo][lane(32)][2 regs]
__device__ u32 g_Bfrag[3][8][16][2][32][2];

// ---------------------------------------------------------------- helpers
__device__ __forceinline__ u32 smem_u32(const void* p) {
    u32 a;
    asm("{ .reg .u64 t; cvta.to.shared.u64 t, %1; cvt.u32.u64 %0, t; }"
        : "=r"(a) : "l"(p));
    return a;
}
__device__ __forceinline__ void mma_bf16(float* c, const u32* a, u32 b0, u32 b1) {
    asm volatile(
        "mma.sync.aligned.m16n8k16.row.col.f32.bf16.bf16.f32 "
        "{%0,%1,%2,%3}, {%4,%5,%6,%7}, {%8,%9}, {%0,%1,%2,%3};"
        : "+f"(c[0]), "+f"(c[1]), "+f"(c[2]), "+f"(c[3])
        : "r"(a[0]), "r"(a[1]), "r"(a[2]), "r"(a[3]), "r"(b0), "r"(b1));
}
__device__ __forceinline__ void ldsm4(u32* r, u32 addr) {
    asm volatile(
        "ldmatrix.sync.aligned.m8n8.x4.shared.b16 {%0,%1,%2,%3}, [%4];"
        : "=r"(r[0]), "=r"(r[1]), "=r"(r[2]), "=r"(r[3]) : "r"(addr));
}
__device__ __forceinline__ u32 pack_bf16(float a, float b) {
    __nv_bfloat162 p = make_bfloat162(__float2bfloat16(a), __float2bfloat16(b));
    return *(u32*)&p;
}

// ---------------------------------------------------------------- prep
__global__ void prep_kernel(const float* __restrict__ W1,
                            const float* __restrict__ W2,
                            const float* __restrict__ W3, int n) {
    int idx = blockIdx.x * 256 + threadIdx.x;
    if (idx < n) { g_cnt[0][idx] = 0; g_cnt[1][idx] = 0; }
    if (idx < 3 * 8192) {
        int lane  = idx & 31;
        int split = (idx >> 5) & 1;
        int nt    = (idx >> 6) & 15;
        int kc    = (idx >> 10) & 7;
        int mtx   = idx >> 13;
        int outc  = (mtx == 2) ? 64 : 128;
        if (nt * 8 < outc) {
            const float* W = (mtx == 0) ? W1 : ((mtx == 1) ? W2 : W3);
            int c  = nt * 8 + (lane >> 2);
            int k0 = kc * 16 + (lane & 3) * 2;
#pragma unroll
            for (int r = 0; r < 2; r++) {
                int k = k0 + 8 * r;
                float w0 = W[k * outc + c];
                float w1 = W[(k + 1) * outc + c];
                u32 val;
                if (split == 0) {
                    val = pack_bf16(w0, w1);
                } else {
                    float h0 = __bfloat162float(__float2bfloat16(w0));
                    float h1 = __bfloat162float(__float2bfloat16(w1));
                    val = pack_bf16(w0 - h0, w1 - h1);
                }
                g_Bfrag[mtx][kc][nt][split][lane][r] = val;
            }
        }
    }
}

// ---------------------------------------------------------------- CSR build
__global__ void count_kernel(const int* __restrict__ se,
                             const int* __restrict__ te, int m) {
    int net = blockIdx.y;
    const int* dst = (net ? te : se) + m;
    for (int e = blockIdx.x * blockDim.x + threadIdx.x; e < m;
         e += gridDim.x * blockDim.x)
        atomicAdd(&g_cnt[net][dst[e]], 1);
}

__global__ void scanA_kernel(int n) {
    __shared__ int ss[1024];
    int net = blockIdx.y;
    int t = threadIdx.x;
    int i = blockIdx.x * 1024 + t;
    int c = (i < n) ? g_cnt[net][i] : 0;
    ss[t] = c;
    __syncthreads();
    for (int d = 1; d < 1024; d <<= 1) {
        int v = (t >= d) ? ss[t - d] : 0;
        __syncthreads();
        ss[t] += v;
        __syncthreads();
    }
    if (i < n) {
        g_off[net][i] = ss[t] - c;
        g_dis[net][i] = rsqrtf((float)(c + 1));
    }
    if (t == 1023) g_bsum[net][blockIdx.x] = ss[1023];
}

__global__ void scanB_kernel(int nb, int n) {
    __shared__ int ss[NB_MAX];
    int net = blockIdx.y;
    int t = threadIdx.x;
    int c = (t < nb) ? g_bsum[net][t] : 0;
    ss[t] = c;
    __syncthreads();
    for (int d = 1; d < NB_MAX; d <<= 1) {
        int v = (t >= d) ? ss[t - d] : 0;
        __syncthreads();
        ss[t] += v;
        __syncthreads();
    }
    if (t < nb) g_bpre[net][t] = ss[t] - c;
    if (t == NB_MAX - 1) g_off[net][n] = ss[NB_MAX - 1];
}

__global__ void scanC_kernel(int n) {
    int net = blockIdx.y;
    int i = blockIdx.x * 1024 + threadIdx.x;
    if (i < n) {
        int v = g_off[net][i] + g_bpre[net][i >> 10];
        g_off[net][i] = v;
        g_cur[net][i] = v;
    }
}

__global__ void fill_kernel(const int* __restrict__ se,
                            const int* __restrict__ te, int m) {
    int net = blockIdx.y;
    const int* src = net ? te : se;
    const int* dst = src + m;
    for (int e = blockIdx.x * blockDim.x + threadIdx.x; e < m;
         e += gridDim.x * blockDim.x) {
        int p = atomicAdd(&g_cur[net][dst[e]], 1);
        g_adj[net][p] = src[e];
    }
}

// ---------------------------------------------------------------- mma GEMM
// g_h[net][r,:] = (relu?)X[r,:] @ W  via bf16-split mma.sync.
// 128-row tile, 256 threads, 2x4 warp grid; warp = 64 rows x OUTC/4 cols.
// B fragments loaded ONCE per warp-kc and reused across 4 row-fragments:
// wavefronts/HMMA drops 1.33 -> 1.0 vs the 32-row warp tile.
template <int OUTC, bool RELU_IN>
__global__ void __launch_bounds__(256, 2)
gemm_mma_kernel(const float* __restrict__ X0, const float* __restrict__ X1,
                int midx0, int midx1, int n) {
    constexpr int PA = 136;
    constexpr int WCOLS = OUTC / 4;       // 32 or 16
    constexpr int NTILE = WCOLS / 8;      // 4 or 2
    constexpr int A_SPLIT = 128 * PA * 2; // bytes per A split (128 rows)

    extern __shared__ char smem[];
    __nv_bfloat16* sAhi = (__nv_bfloat16*)smem;
    __nv_bfloat16* sAlo = (__nv_bfloat16*)(smem + A_SPLIT);

    int tid = threadIdx.x;
    int net = blockIdx.y;
    const float* X = net ? X1 : X0;
    int midx = net ? midx1 : midx0;
    int row0 = blockIdx.x * 128;
    float* H = g_h[net];

    // stage X -> bf16 hi/lo (128 rows x 128 cols; 2 threads per row)
    {
        int r = tid >> 1;
        int c0 = (tid & 1) * 64;
        int gr = row0 + r;
        const float4* xrow = (const float4*)(X + (size_t)gr * 128 + c0);
        u32* ah = (u32*)&sAhi[r * PA + c0];
        u32* al = (u32*)&sAlo[r * PA + c0];
#pragma unroll
        for (int j = 0; j < 16; j++) {
            float4 v = make_float4(0.f, 0.f, 0.f, 0.f);
            if (gr < n) v = xrow[j];
            if (RELU_IN) {
                v.x = fmaxf(v.x, 0.f); v.y = fmaxf(v.y, 0.f);
                v.z = fmaxf(v.z, 0.f); v.w = fmaxf(v.w, 0.f);
            }
            float hx = __bfloat162float(__float2bfloat16(v.x));
            float hy = __bfloat162float(__float2bfloat16(v.y));
            float hz = __bfloat162float(__float2bfloat16(v.z));
            float hw = __bfloat162float(__float2bfloat16(v.w));
            ah[2 * j]     = pack_bf16(v.x, v.y);
            ah[2 * j + 1] = pack_bf16(v.z, v.w);
            al[2 * j]     = pack_bf16(v.x - hx, v.y - hy);
            al[2 * j + 1] = pack_bf16(v.z - hz, v.w - hw);
        }
    }
    __syncthreads();

    int lane = tid & 31, w = tid >> 5;
    int rowg = w >> 2, colg = w & 3;    // 2 x 4 warp grid; warp = 64r x WCOLS

    u32 sAhi_u = smem_u32(sAhi), sAlo_u = smem_u32(sAlo);
    u32 aoff = ((rowg * 64 + (lane & 15)) * PA + ((lane >> 4) << 3)) * 2;

    const uint2* bfr = (const uint2*)g_Bfrag[midx];

    float acc[NTILE][4][4];
#pragma unroll
    for (int t = 0; t < NTILE; t++)
#pragma unroll
        for (int fr = 0; fr < 4; fr++)
#pragma unroll
            for (int i = 0; i < 4; i++) acc[t][fr][i] = 0.f;

#pragma unroll
    for (int kc = 0; kc < 8; kc++) {
        // B fragments: loaded once per warp-kc, reused for 4 row-frags
        uint2 bh[NTILE], bl[NTILE];
#pragma unroll
        for (int t = 0; t < NTILE; t++) {
            int ntg = colg * NTILE + t;
            bh[t] = __ldg(&bfr[((kc * 16 + ntg) * 2 + 0) * 32 + lane]);
            bl[t] = __ldg(&bfr[((kc * 16 + ntg) * 2 + 1) * 32 + lane]);
        }
#pragma unroll
        for (int fr = 0; fr < 4; fr++) {
            u32 ah[4], al[4];
            ldsm4(ah, sAhi_u + aoff + fr * (16 * PA * 2) + kc * 32);
            ldsm4(al, sAlo_u + aoff + fr * (16 * PA * 2) + kc * 32);
#pragma unroll
            for (int t = 0; t < NTILE; t++) {
                mma_bf16(acc[t][fr], ah, bh[t].x, bh[t].y);
                mma_bf16(acc[t][fr], al, bh[t].x, bh[t].y);
                mma_bf16(acc[t][fr], ah, bl[t].x, bl[t].y);
            }
        }
    }

    // epilogue
    {
        int qrow = lane >> 2, qk = (lane & 3) * 2;
#pragma unroll
        for (int fr = 0; fr < 4; fr++) {
            int gr0 = row0 + rowg * 64 + fr * 16 + qrow;
            int gr1 = gr0 + 8;
#pragma unroll
            for (int t = 0; t < NTILE; t++) {
                int col = colg * WCOLS + t * 8 + qk;
                if (gr0 < n) {
                    float2 v = make_float2(acc[t][fr][0], acc[t][fr][1]);
                    *(float2*)&H[(size_t)gr0 * OUTC + col] = v;
                }
                if (gr1 < n) {
                    float2 v = make_float2(acc[t][fr][2], acc[t][fr][3]);
                    *(float2*)&H[(size_t)gr1 * OUTC + col] = v;
                }
            }
        }
    }
}

// ---------------------------------------------------------------- aggregation
// out[w] = dis[w]*(h[w]*dis[w] + sum_s h[s]*dis[s]) + bias    (4-way MLP)
__global__ void agg128_kernel(const float* __restrict__ b1,
                              const float* __restrict__ b2, int n) {
    int net = blockIdx.y;
    int w = (blockIdx.x * blockDim.x + threadIdx.x) >> 5;
    int lane = threadIdx.x & 31;
    if (w >= n) return;
    const float4* H4 = (const float4*)g_h[net];
    const float* bias = net ? b2 : b1;
    const float* dis = g_dis[net];
    float dw = dis[w];
    float4 self = H4[(size_t)w * 32 + lane];
    float4 acc = make_float4(self.x * dw, self.y * dw, self.z * dw, self.w * dw);
    int j = g_off[net][w], e0 = g_off[net][w + 1];
    const int* adj = g_adj[net];
    for (; j + 4 <= e0; j += 4) {
        int s0 = __ldg(&adj[j]), s1 = __ldg(&adj[j + 1]);
        int s2 = __ldg(&adj[j + 2]), s3 = __ldg(&adj[j + 3]);
        float4 v0 = H4[(size_t)s0 * 32 + lane];
        float4 v1 = H4[(size_t)s1 * 32 + lane];
        float4 v2 = H4[(size_t)s2 * 32 + lane];
        float4 v3 = H4[(size_t)s3 * 32 + lane];
        float d0 = __ldg(&dis[s0]), d1 = __ldg(&dis[s1]);
        float d2 = __ldg(&dis[s2]), d3 = __ldg(&dis[s3]);
        acc.x += v0.x * d0 + v1.x * d1 + v2.x * d2 + v3.x * d3;
        acc.y += v0.y * d0 + v1.y * d1 + v2.y * d2 + v3.y * d3;
        acc.z += v0.z * d0 + v1.z * d1 + v2.z * d2 + v3.z * d3;
        acc.w += v0.w * d0 + v1.w * d1 + v2.w * d2 + v3.w * d3;
    }
    for (; j < e0; j++) {
        int s = __ldg(&adj[j]);
        float dsn = __ldg(&dis[s]);
        float4 v = H4[(size_t)s * 32 + lane];
        acc.x += v.x * dsn; acc.y += v.y * dsn;
        acc.z += v.z * dsn; acc.w += v.w * dsn;
    }
    float4 bb = ((const float4*)bias)[lane];
    acc.x = acc.x * dw + bb.x;
    acc.y = acc.y * dw + bb.y;
    acc.z = acc.z * dw + bb.z;
    acc.w = acc.w * dw + bb.w;
    ((float4*)g_hs[net])[(size_t)w * 32 + lane] = acc;
}

__global__ void agg64_kernel(const float* __restrict__ bias,
                             float* __restrict__ zs,
                             float* __restrict__ zt, int n) {
    int net = blockIdx.y;
    int w = (blockIdx.x * blockDim.x + threadIdx.x) >> 5;
    int lane = threadIdx.x & 31;
    if (w >= n) return;
    const float2* H2 = (const float2*)g_h[net];
    const float* dis = g_dis[net];
    float dw = dis[w];
    float2 self = H2[(size_t)w * 32 + lane];
    float2 acc = make_float2(self.x * dw, self.y * dw);
    int j = g_off[net][w], e0 = g_off[net][w + 1];
    const int* adj = g_adj[net];
    for (; j + 4 <= e0; j += 4) {
        int s0 = __ldg(&adj[j]), s1 = __ldg(&adj[j + 1]);
        int s2 = __ldg(&adj[j + 2]), s3 = __ldg(&adj[j + 3]);
        float2 v0 = H2[(size_t)s0 * 32 + lane];
        float2 v1 = H2[(size_t)s1 * 32 + lane];
        float2 v2 = H2[(size_t)s2 * 32 + lane];
        float2 v3 = H2[(size_t)s3 * 32 + lane];
        float d0 = __ldg(&dis[s0]), d1 = __ldg(&dis[s1]);
        float d2 = __ldg(&dis[s2]), d3 = __ldg(&dis[s3]);
        acc.x += v0.x * d0 + v1.x * d1 + v2.x * d2 + v3.x * d3;
        acc.y += v0.y * d0 + v1.y * d1 + v2.y * d2 + v3.y * d3;
    }
    for (; j < e0; j++) {
        int s = __ldg(&adj[j]);
        float dsn = __ldg(&dis[s]);
        float2 v = H2[(size_t)s * 32 + lane];
        acc.x += v.x * dsn;
        acc.y += v.y * dsn;
    }
    float2 bb = ((const float2*)bias)[lane];
    acc.x = acc.x * dw + bb.x;
    acc.y = acc.y * dw + bb.y;
    float* Out = net ? zt : zs;
    ((float2*)Out)[(size_t)w * 32 + lane] = acc;
}

// ---------------------------------------------------------------- decoder
__global__ void decoder_kernel(const float* __restrict__ zs,
                               const float* __restrict__ zt,
                               const int* __restrict__ se,
                               const int* __restrict__ te,
                               float* __restrict__ P, int m) {
    int gid = blockIdx.x * blockDim.x + threadIdx.x;
    int e = gid >> 4;
    int l = gid & 15;
    int ec = min(e, 2 * m - 1);
    int net = (ec >= m);
    int el = net ? (ec - m) : ec;
    const int* ea = net ? te : se;
    const float* Z = net ? zt : zs;
    int a = ea[el], b = ea[el + m];
    const float4* Z4 = (const float4*)Z;
    float4 va = Z4[(size_t)a * 16 + l];
    float4 vb = Z4[(size_t)b * 16 + l];
    float s = va.x * vb.x + va.y * vb.y + va.z * vb.z + va.w * vb.w;
    s += __shfl_xor_sync(0xffffffffu, s, 8);
    s += __shfl_xor_sync(0xffffffffu, s, 4);
    s += __shfl_xor_sync(0xffffffffu, s, 2);
    s += __shfl_xor_sync(0xffffffffu, s, 1);
    if (l == 0 && e < 2 * m) P[e] = 1.0f / (1.0f + expf(-s));
}

// ---------------------------------------------------------------- launch
extern "C" void kernel_launch(void* const* d_in, const int* in_sizes, int n_in,
                              void* d_out, int out_size) {
    const float* xs = (const float*)d_in[0];
    const float* xt = (const float*)d_in[1];
    const int*   se = (const int*)d_in[2];
    const int*   te = (const int*)d_in[3];
    const float* W1 = (const float*)d_in[4];
    const float* b1 = (const float*)d_in[5];
    const float* W2 = (const float*)d_in[6];
    const float* b2 = (const float*)d_in[7];
    const float* W3 = (const float*)d_in[8];
    const float* b3 = (const float*)d_in[9];

    int n = in_sizes[0] / 128;   // 100000
    int m = in_sizes[2] / 2;     // 500000

    float* out = (float*)d_out;
    float* zs = out;
    float* zt = out + (size_t)n * 64;
    float* ps = zt + (size_t)n * 64;

    float *hsbuf;
    cudaGetSymbolAddress((void**)&hsbuf, g_hs);

    const int SMA = 2 * (128 * 136 * 2);   // 69632 bytes (A hi+lo, 128 rows)
    cudaFuncSetAttribute(gemm_mma_kernel<128, false>,
                         cudaFuncAttributeMaxDynamicSharedMemorySize, SMA);
    cudaFuncSetAttribute(gemm_mma_kernel<64, true>,
                         cudaFuncAttributeMaxDynamicSharedMemorySize, SMA);

    int nb = (n + 1023) / 1024;  // 98
    dim3 gm512((m + 511) / 512, 2);
    dim3 gscan(nb, 2);
    dim3 gone(1, 2);
    dim3 gtc((n + 127) / 128, 2);
    dim3 gagg((n + 7) / 8, 2);
    int gb_dec = (2 * m + 15) / 16;

    // Side stream + fork/join events (R12/R16 topology — passed mem-guard 3x).
    cudaStream_t s2;
    cudaStreamCreateWithFlags(&s2, cudaStreamNonBlocking);
    cudaEvent_t ev1, ev2;
    cudaEventCreateWithFlags(&ev1, cudaEventDisableTiming);
    cudaEventCreateWithFlags(&ev2, cudaEventDisableTiming);

    // prep: Bfrag + zeroed counters
    prep_kernel<<<(n + 255) / 256, 256>>>(W1, W2, W3, n);
    cudaEventRecord(ev1, 0);
    cudaStreamWaitEvent(s2, ev1, 0);

    // CSR chain on side stream, overlapped with gemm128 on main stream
    count_kernel<<<gm512, 512, 0, s2>>>(se, te, m);
    scanA_kernel<<<gscan, 1024, 0, s2>>>(n);
    gemm_mma_kernel<128, false><<<gtc, 256, SMA>>>(xs, xt, 0, 1, n);
    scanB_kernel<<<gone, NB_MAX, 0, s2>>>(nb, n);
    scanC_kernel<<<gscan, 1024, 0, s2>>>(n);
    fill_kernel<<<gm512, 512, 0, s2>>>(se, te, m);
    cudaEventRecord(ev2, s2);
    cudaStreamWaitEvent(0, ev2, 0);

    agg128_kernel<<<gagg, 256>>>(b1, b2, n);
    gemm_mma_kernel<64, true><<<gtc, 256, SMA>>>(hsbuf,
                                                 hsbuf + (size_t)NN * 128,
                                                 2, 2, n);
    agg64_kernel<<<gagg, 256>>>(b3, zs, zt, n);
    decoder_kernel<<<gb_dec, 256>>>(zs, zt, se, te, ps, m);
}